// round 5
// baseline (speedup 1.0000x reference)
#include <cuda_runtime.h>
#include <cuda_bf16.h>

// ============================================================================
// EmbeddingDropout: out[b,s,:] = dropout(weight, p=0.1, jax key 42)[words[b,s], :]
//
// Mask: jax threefry2x32 partitionable counter mode (confirmed bit-exact R2):
//   (o0,o1) = threefry2x32(key=(0,42), x0=0, x1=flat_index); bits = o0^o1
//   keep <=> bits < 0xE6666600u ; out = keep ? w/0.9 : 0
//
// Perf strategy (R3/R4/R5): kernel was alu-pipe-bound (83.8%) with fma idle
// (24.8%). SHF/LOP3 must stay on the alu pipe, but every threefry ADD is
// forced onto the fma pipe as IMAD (y*one + x, `one` an opaque device global
// == 1), cutting alu work per round from ~2.5 instrs to 2. Index-dtype
// detection is inlined (warp ballot over first 64 ints) to drop a launch.
// ============================================================================

#define KEEP_THRESH 0xE6666600u   // 7549747 << 9  (7549747*2^-23 == 0.9f exactly)
#define D_COLS      1024

// Opaque 1: ptxas cannot constant-fold a mutable __device__ global, so
// y*g_one + x must be emitted as IMAD (fma pipe), not IADD3 (alu pipe).
__device__ unsigned int g_one = 1u;

__device__ __forceinline__ unsigned int rotl32(unsigned int x, int r) {
    return __funnelshift_l(x, x, r);   // single SHF.L.W (alu pipe)
}

// x + y via IMAD on the fma pipe.
__device__ __forceinline__ unsigned int addm(unsigned int x, unsigned int y,
                                             unsigned int one) {
    return y * one + x;
}

// Threefry-2x32, key (0, 42), block (0, ctr); returns o0 ^ o1.
// All adds routed through IMAD (fma pipe) via `one`.
__device__ __forceinline__ unsigned int tf_bits(unsigned int ctr, unsigned int one) {
    const unsigned int ks1 = 42u;
    const unsigned int ks2 = 0x1BD11BF0u;  // 0 ^ 42 ^ 0x1BD11BDA
    unsigned int x0 = 0u;                  // + ks0 (= 0)
    unsigned int x1 = addm(ctr, ks1, one);

#define TF_ROUND(r) { x0 = addm(x0, x1, one); x1 = rotl32(x1, (r)) ^ x0; }
    TF_ROUND(13) TF_ROUND(15) TF_ROUND(26) TF_ROUND(6)
    x0 = addm(x0, ks1, one);        x1 = addm(x1, ks2 + 1u, one);
    TF_ROUND(17) TF_ROUND(29) TF_ROUND(16) TF_ROUND(24)
    x0 = addm(x0, ks2, one);        x1 = addm(x1, 0u + 2u, one);
    TF_ROUND(13) TF_ROUND(15) TF_ROUND(26) TF_ROUND(6)
    /* x0 += 0 */                   x1 = addm(x1, ks1 + 3u, one);
    TF_ROUND(17) TF_ROUND(29) TF_ROUND(16) TF_ROUND(24)
    x0 = addm(x0, ks1, one);        x1 = addm(x1, ks2 + 4u, one);
    TF_ROUND(13) TF_ROUND(15) TF_ROUND(26) TF_ROUND(6)
    x0 = addm(x0, ks2, one);        x1 = addm(x1, 0u + 5u, one);
#undef TF_ROUND
    return x0 ^ x1;
}

__global__ __launch_bounds__(256)
void EmbeddingDropout_15152644620959_kernel(
    const unsigned int* __restrict__ words32,
    const float* __restrict__ weight,
    float* __restrict__ out)
{
    const int row = blockIdx.x;            // flat (b, s) index
    const int tid = threadIdx.x;           // 256 threads, 4 cols each -> 1024

    const unsigned int one = g_one;        // opaque 1 (LDG, L1-hot)

    // Inline dtype detection: for little-endian int64 ids (< 50257) every odd
    // 32-bit lane of the first 64 is zero; for int32 data they're random ids.
    // The 256B region is L1/L2-resident for every block.
    const unsigned int lane = tid & 31u;
    const unsigned int oddv = __ldg(words32 + 2u * lane + 1u);
    const bool is64 = __all_sync(0xFFFFFFFFu, oddv == 0u);

    // Broadcast load of this row's vocab id.
    const unsigned int word = is64 ? __ldg(words32 + 2u * (unsigned)row)
                                   : __ldg(words32 + (unsigned)row);

    const unsigned int c0    = (unsigned int)tid * 4u;
    const unsigned int fbase = word * (unsigned int)D_COLS + c0;   // IMAD

    const float4 w4 = __ldg((const float4*)(weight + (size_t)word * D_COLS + c0));

    // Four independent threefry evals -> ILP across both pipes.
    const unsigned int b0 = tf_bits(fbase + 0u, one);
    const unsigned int b1 = tf_bits(fbase + 1u, one);
    const unsigned int b2 = tf_bits(fbase + 2u, one);
    const unsigned int b3 = tf_bits(fbase + 3u, one);

    const float inv_keep = 1.0f / 0.9f;
    float4 o;
    o.x = (b0 < KEEP_THRESH) ? w4.x * inv_keep : 0.0f;
    o.y = (b1 < KEEP_THRESH) ? w4.y * inv_keep : 0.0f;
    o.z = (b2 < KEEP_THRESH) ? w4.z * inv_keep : 0.0f;
    o.w = (b3 < KEEP_THRESH) ? w4.w * inv_keep : 0.0f;

    *(float4*)(out + (size_t)row * D_COLS + c0) = o;
}

extern "C" void kernel_launch(void* const* d_in, const int* in_sizes, int n_in,
                              void* d_out, int out_size) {
    const unsigned int* words  = (const unsigned int*)d_in[0]; // int32/int64 ids
    const float*        weight = (const float*)d_in[1];        // [50257,1024] f32
    float*              out    = (float*)d_out;                // [B*S,1024] f32

    const int rows = out_size / D_COLS;            // 16384

    EmbeddingDropout_15152644620959_kernel<<<rows, 256>>>(words, weight, out);
}

// round 16
// speedup vs baseline: 1.0359x; 1.0359x over previous
#include <cuda_runtime.h>
#include <cuda_bf16.h>

// ============================================================================
// EmbeddingDropout: out[b,s,:] = dropout(weight, p=0.1, jax key 42)[words[b,s], :]
//
// Mask: jax threefry2x32 partitionable counter mode (confirmed bit-exact R2):
//   (o0,o1) = threefry2x32(key=(0,42), x0=0, x1=flat_index); bits = o0^o1
//   keep <=> bits < 0xE6666600u ; out = keep ? w/0.9 : 0
//
// R6-R15: revert R5's IMAD re-pipe (proved slower: binder is total issue
// slots + threefry dependency chains, not alu-pipe throughput). Single launch.
// Change under test: 2 rows per block -> 8 independent threefry chains per
// thread (was 4), doubling ILP to hide the 8-cyc/round RAW latency and the
// word-load scoreboard wait.
// ============================================================================

#define KEEP_THRESH 0xE6666600u   // 7549747 << 9  (7549747*2^-23 == 0.9f exactly)
#define D_COLS      1024

__device__ __forceinline__ unsigned int rotl32(unsigned int x, int r) {
    return __funnelshift_l(x, x, r);   // single SHF (alu pipe)
}

// Threefry-2x32, key (0, 42), block (0, ctr); returns o0 ^ o1.
__device__ __forceinline__ unsigned int tf_bits(unsigned int ctr) {
    const unsigned int ks1 = 42u;
    const unsigned int ks2 = 0x1BD11BF0u;  // 0 ^ 42 ^ 0x1BD11BDA
    unsigned int x0 = 0u;                  // + ks0 (= 0)
    unsigned int x1 = ctr + ks1;

#define TF_ROUND(r) { x0 += x1; x1 = rotl32(x1, (r)) ^ x0; }
    TF_ROUND(13) TF_ROUND(15) TF_ROUND(26) TF_ROUND(6)
    x0 += ks1;  x1 += ks2 + 1u;
    TF_ROUND(17) TF_ROUND(29) TF_ROUND(16) TF_ROUND(24)
    x0 += ks2;  x1 += 0u  + 2u;
    TF_ROUND(13) TF_ROUND(15) TF_ROUND(26) TF_ROUND(6)
    /* x0 += 0 */ x1 += ks1 + 3u;
    TF_ROUND(17) TF_ROUND(29) TF_ROUND(16) TF_ROUND(24)
    x0 += ks1;  x1 += ks2 + 4u;
    TF_ROUND(13) TF_ROUND(15) TF_ROUND(26) TF_ROUND(6)
    x0 += ks2;  x1 += 0u  + 5u;
#undef TF_ROUND
    return x0 ^ x1;
}

__device__ __forceinline__ float4 mask_row(float4 w4, unsigned int fbase) {
    const unsigned int b0 = tf_bits(fbase + 0u);
    const unsigned int b1 = tf_bits(fbase + 1u);
    const unsigned int b2 = tf_bits(fbase + 2u);
    const unsigned int b3 = tf_bits(fbase + 3u);
    const float inv_keep = 1.0f / 0.9f;
    float4 o;
    o.x = (b0 < KEEP_THRESH) ? w4.x * inv_keep : 0.0f;
    o.y = (b1 < KEEP_THRESH) ? w4.y * inv_keep : 0.0f;
    o.z = (b2 < KEEP_THRESH) ? w4.z * inv_keep : 0.0f;
    o.w = (b3 < KEEP_THRESH) ? w4.w * inv_keep : 0.0f;
    return o;
}

__global__ __launch_bounds__(256)
void EmbeddingDropout_15152644620959_kernel(
    const unsigned int* __restrict__ words32,
    const float* __restrict__ weight,
    float* __restrict__ out)
{
    const int tid  = threadIdx.x;             // 256 threads, 4 cols each
    const int row0 = blockIdx.x * 2;          // this block covers rows row0, row0+1
    const int row1 = row0 + 1;

    // Inline dtype detection: little-endian int64 ids (< 50257) have all odd
    // 32-bit lanes zero in the first 64 words; int32 ids are random there.
    const unsigned int lane = tid & 31u;
    const unsigned int oddv = __ldg(words32 + 2u * lane + 1u);
    const bool is64 = __all_sync(0xFFFFFFFFu, oddv == 0u);

    // Two broadcast word loads (independent).
    const unsigned int w0 = is64 ? __ldg(words32 + 2u * (unsigned)row0)
                                 : __ldg(words32 + (unsigned)row0);
    const unsigned int w1 = is64 ? __ldg(words32 + 2u * (unsigned)row1)
                                 : __ldg(words32 + (unsigned)row1);

    const unsigned int c0 = (unsigned int)tid * 4u;

    // Two independent gathers — both LDGs issue before any threefry math.
    const float4 a4 = __ldg((const float4*)(weight + (size_t)w0 * D_COLS + c0));
    const float4 b4 = __ldg((const float4*)(weight + (size_t)w1 * D_COLS + c0));

    // 8 independent threefry chains across the two rows.
    const float4 oa = mask_row(a4, w0 * (unsigned)D_COLS + c0);
    const float4 ob = mask_row(b4, w1 * (unsigned)D_COLS + c0);

    *(float4*)(out + (size_t)row0 * D_COLS + c0) = oa;
    *(float4*)(out + (size_t)row1 * D_COLS + c0) = ob;
}

extern "C" void kernel_launch(void* const* d_in, const int* in_sizes, int n_in,
                              void* d_out, int out_size) {
    const unsigned int* words  = (const unsigned int*)d_in[0]; // int32/int64 ids
    const float*        weight = (const float*)d_in[1];        // [50257,1024] f32
    float*              out    = (float*)d_out;                // [B*S,1024] f32

    const int rows = out_size / D_COLS;            // 16384
    EmbeddingDropout_15152644620959_kernel<<<rows / 2, 256>>>(words, weight, out);
}